// round 8
// baseline (speedup 1.0000x reference)
#include <cuda_runtime.h>
#include <cuda_bf16.h>
#include <cooperative_groups.h>
#include <math.h>

namespace cg = cooperative_groups;

#define Bsz 32
#define Ssz 1024
#define Hsz 256
#define G4  1024
#define WSR 27              // SMEM W_hh rows per gates-warp
#define WRR 5               // register-resident W_hh rows per gates-warp
#define NSM (8 * WSR)       // 216 rows in SMEM (216 + 40 reg = 256 owned rows)

// scratch: WX[b,s,j] = enc[b,s,:]·W_ih[j,:] + b_ih[j] + b_hh[j]
__device__ float g_WX[(size_t)Bsz * Ssz * G4];

__device__ __forceinline__ float dot8(float4 a0, float4 a1, float4 h0, float4 h1) {
  return a0.x*h0.x + a0.y*h0.y + a0.z*h0.z + a0.w*h0.w
       + a1.x*h1.x + a1.y*h1.y + a1.z*h1.z + a1.w*h1.w;
}
__device__ __forceinline__ float wsum(float acc) {
#pragma unroll
  for (int o = 16; o; o >>= 1) acc += __shfl_down_sync(0xffffffffu, acc, o);
  return acc;
}

// ---------------------------------------------------------------------------
// Kernel 1: WX = enc @ W_ih^T + (b_ih + b_hh)   (fp32 tiled GEMM) — proven R5
// ---------------------------------------------------------------------------
__global__ __launch_bounds__(256) void wx_gemm(
    const float* __restrict__ A,
    const float* __restrict__ Wb,
    const float* __restrict__ b_ih,
    const float* __restrict__ b_hh)
{
  __shared__ float As[16][64];
  __shared__ float Bs[16][64];
  const int tid  = threadIdx.x;
  const int row0 = blockIdx.y * 64;
  const int col0 = blockIdx.x * 64;
  const int lr = tid >> 2;
  const int lc = (tid & 3) * 4;
  const int ty = tid >> 4, tx = tid & 15;
  float acc[4][4] = {};

  for (int k0 = 0; k0 < 256; k0 += 16) {
    float4 av = *(const float4*)(A  + (size_t)(row0 + lr) * 256 + k0 + lc);
    float4 bv = *(const float4*)(Wb + (size_t)(col0 + lr) * 256 + k0 + lc);
    As[lc + 0][lr] = av.x; As[lc + 1][lr] = av.y;
    As[lc + 2][lr] = av.z; As[lc + 3][lr] = av.w;
    Bs[lc + 0][lr] = bv.x; Bs[lc + 1][lr] = bv.y;
    Bs[lc + 2][lr] = bv.z; Bs[lc + 3][lr] = bv.w;
    __syncthreads();
#pragma unroll
    for (int kk = 0; kk < 16; kk++) {
      float4 a4 = *(const float4*)&As[kk][ty * 4];
      float4 b4 = *(const float4*)&Bs[kk][tx * 4];
      float a[4]  = {a4.x, a4.y, a4.z, a4.w};
      float bb[4] = {b4.x, b4.y, b4.z, b4.w};
#pragma unroll
      for (int i = 0; i < 4; i++)
#pragma unroll
        for (int j = 0; j < 4; j++) acc[i][j] += a[i] * bb[j];
    }
    __syncthreads();
  }
#pragma unroll
  for (int i = 0; i < 4; i++) {
    int rr = row0 + ty * 4 + i;
#pragma unroll
    for (int j = 0; j < 4; j++) {
      int cc = col0 + tx * 4 + j;
      g_WX[(size_t)rr * G4 + cc] = acc[i][j] + b_ih[cc] + b_hh[cc];
    }
  }
}

// ---------------------------------------------------------------------------
// Kernel 2: sequential decoder. One 4-CTA cluster per batch.
// warps 0-7: scores (enc·h, L2 stream)  ∥  warps 8-15: W_hh·h (SMEM+regs)
// Loop invariant: at top of iter t, h(t+1) is in h_buf[t&1]; out row t uses it.
// ---------------------------------------------------------------------------
__global__ void __cluster_dims__(4, 1, 1) __launch_bounds__(512, 1)
decoder_main(const float* __restrict__ enc,
             const float* __restrict__ W_hh,
             const float* __restrict__ b_ih,
             const float* __restrict__ b_hh,
             float* __restrict__ out)
{
  extern __shared__ float smf[];
  float* Wsm      = smf;                    // NSM*256
  float* h_buf    = Wsm + NSM * 256;        // 2*256
  float* c_s      = h_buf + 512;            // 64
  float* gates_s  = c_s + 64;               // 256
  float* scores_s = gates_s + 256;          // 256
  float* red_m    = scores_s + 256;         // 8
  int*   red_i    = (int*)(red_m + 8);      // 8
  float* tup_m    = (float*)(red_i + 8);    // 4
  int*   tup_i    = (int*)(tup_m + 4);      // 4

  cg::cluster_group cluster = cg::this_cluster();
  const int tid  = threadIdx.x;
  const int w    = tid >> 5, lane = tid & 31;
  const int r    = blockIdx.x & 3;
  const int b    = blockIdx.x >> 2;
  const float4* Wh4 = (const float4*)W_hh;

  // ---- init: SMEM W rows (first WSR of each gates-warp's 32) ----
  for (int i = tid; i < NSM * 64; i += 512) {
    int slot = i >> 6, c4 = i & 63;
    int w8 = slot / WSR, lrr = slot - w8 * WSR;
    int l = w8 * 32 + lrr;
    int G = (l >> 6) * 256 + r * 64 + (l & 63);
    ((float4*)Wsm)[i] = Wh4[(size_t)G * 64 + c4];
  }
  // ---- register-resident W rows (gates warps; last WRR of each 32) ----
  float4 wr0[WRR], wr1[WRR];
  if (w >= 8) {
    int w8 = w - 8;
#pragma unroll
    for (int j = 0; j < WRR; j++) {
      int l = w8 * 32 + WSR + j;
      int G = (l >> 6) * 256 + r * 64 + (l & 63);
      wr0[j] = Wh4[(size_t)G * 64 + lane];
      wr1[j] = Wh4[(size_t)G * 64 + 32 + lane];
    }
  }

  // ---- prologue: h(1), c(1) from bias-only gates (h0=0, c0=0, x0=0) ----
  // (fma(f,0,x)==x exactly, so iv*gv / iv*tanh(gg) match the R5 path bitwise)
  if (tid < 256) {
    float gi = b_ih[tid]       + b_hh[tid];
    float gg = b_ih[512 + tid] + b_hh[512 + tid];
    float go = b_ih[768 + tid] + b_hh[768 + tid];
    float iv = 1.f / (1.f + expf(-gi));
    float gv = tanhf(gg);
    float ov = 1.f / (1.f + expf(-go));
    h_buf[tid] = ov * tanhf(iv * gv);
  }
  if (tid >= 256 && tid < 320) {
    int j = tid - 256, k = r * 64 + j;
    float gi = b_ih[k] + b_hh[k];
    float gg = b_ih[512 + k] + b_hh[512 + k];
    c_s[j] = (1.f / (1.f + expf(-gi))) * tanhf(gg);
  }
  __syncthreads();   // every CTA computed h(1) redundantly — no exchange needed

  const float4* erb = (const float4*)(enc + ((size_t)b * Ssz + r * 256 + w * 32) * Hsz);
  float* outb = out + (size_t)b * Ssz * Ssz + r * 256;
  const float* WXb = g_WX + (size_t)b * Ssz * G4;

#pragma unroll 1
  for (int t = 0; t < Ssz; t++) {
    const int p = t & 1;

    // prefetch first 2 enc rows (static addresses) before the h barrier
    float4 pa0, pa1, pb0, pb1;
    if (w < 8) {
      pa0 = erb[lane];       pa1 = erb[32 + lane];
      pb0 = erb[64 + lane];  pb1 = erb[96 + lane];
    }
    if (t > 0) asm volatile("barrier.cluster.wait.aligned;" ::: "memory");

    const float4* h4 = (const float4*)(h_buf + p * 256);
    float4 h0 = h4[lane], h1 = h4[32 + lane];

    if (w < 8) {
      // ---- scores for rows r*256 + w*32 + [0,32) with running (max,idx) ----
      float m = -INFINITY; int mi = 0;
      {
        float acc = wsum(dot8(pa0, pa1, h0, h1));
        if (lane == 0) { scores_s[w*32] = acc; if (acc > m) { m = acc; mi = w*32; } }
      }
      {
        float acc = wsum(dot8(pb0, pb1, h0, h1));
        if (lane == 0) { scores_s[w*32+1] = acc; if (acc > m) { m = acc; mi = w*32+1; } }
      }
#pragma unroll 3
      for (int ii = 2; ii < 32; ii++) {
        float4 e0 = erb[ii*64 + lane], e1 = erb[ii*64 + 32 + lane];
        float acc = wsum(dot8(e0, e1, h0, h1));
        if (lane == 0) {
          scores_s[w*32 + ii] = acc;
          if (acc > m) { m = acc; mi = w*32 + ii; }
        }
      }
      if (lane == 0) { red_m[w] = m; red_i[w] = r * 256 + mi; }
    } else {
      // ---- recurrent GEMV: gates_s[l] = W_hh[G(l)]·h ----
      int w8 = w - 8;
      const float4* ws = (const float4*)Wsm + (size_t)w8 * WSR * 64;
#pragma unroll 3
      for (int ii = 0; ii < WSR; ii++) {
        float4 a0 = ws[ii*64 + lane], a1 = ws[ii*64 + 32 + lane];
        float acc = wsum(dot8(a0, a1, h0, h1));
        if (lane == 0) gates_s[w8*32 + ii] = acc;
      }
#pragma unroll
      for (int j = 0; j < WRR; j++) {
        float acc = wsum(dot8(wr0[j], wr1[j], h0, h1));
        if (lane == 0) gates_s[w8*32 + WSR + j] = acc;
      }
    }
    __syncthreads();

    // ---- CTA tuple (max, argmax); broadcast to all 4 CTAs via DSMEM ----
    if (w == 8) {
      float m = (lane < 8) ? red_m[lane] : -INFINITY;
      int  mi = (lane < 8) ? red_i[lane] : 0x7fffffff;
#pragma unroll
      for (int o = 4; o; o >>= 1) {
        float om = __shfl_down_sync(0xffffffffu, m, o);
        int   oi = __shfl_down_sync(0xffffffffu, mi, o);
        if (om > m || (om == m && oi < mi)) { m = om; mi = oi; }
      }
      if (lane == 0) {
#pragma unroll
        for (int dst = 0; dst < 4; dst++) {
          *cluster.map_shared_rank(&tup_m[r], dst) = m;
          *cluster.map_shared_rank(&tup_i[r], dst) = mi;
        }
      }
    }
    // raw scores -> out (softmax deferred to finalize kernel)
    if (tid < 64)
      ((float4*)(outb + (size_t)t * Ssz))[tid] = ((const float4*)scores_s)[tid];

    cluster.sync();   // tuples visible cluster-wide

    // combine 4 tuples: ranks cover ascending index ranges, strict > keeps
    // the lowest index on ties (matches jnp.argmax)
    float gm = tup_m[0]; int idx = tup_i[0];
#pragma unroll
    for (int q = 1; q < 4; q++) {
      float mq = tup_m[q];
      if (mq > gm) { gm = mq; idx = tup_i[q]; }
    }

    if (t < Ssz - 1) {
      // ---- cell: h(t+2) = LSTM(gates + WX[idx], c) ; broadcast h ----
      if (tid >= 256 && tid < 320) {
        int j = tid - 256;
        const float* wxr = WXb + (size_t)idx * G4 + r * 64 + j;
        float gi = gates_s[j]        + wxr[0];
        float gf = gates_s[64  + j]  + wxr[256];
        float gg = gates_s[128 + j]  + wxr[512];
        float go = gates_s[192 + j]  + wxr[768];
        float iv = 1.f / (1.f + expf(-gi));
        float fv = 1.f / (1.f + expf(-gf));
        float gv = tanhf(gg);
        float ov = 1.f / (1.f + expf(-go));
        float c  = fv * c_s[j] + iv * gv;
        c_s[j] = c;
        float hk = ov * tanhf(c);
        float* hl = &h_buf[(p ^ 1) * 256 + r * 64 + j];
#pragma unroll
        for (int dst = 0; dst < 4; dst++)
          *cluster.map_shared_rank(hl, dst) = hk;
      }
      asm volatile("barrier.cluster.arrive.aligned;" ::: "memory");
    }
  }
}

// ---------------------------------------------------------------------------
// Kernel 3: softmax finalize (in-place over out rows of 1024)
// ---------------------------------------------------------------------------
__global__ __launch_bounds__(256) void softmax_finalize(float* __restrict__ out)
{
  __shared__ float rmx[8];
  __shared__ float rsm[8];
  const int tid = threadIdx.x, w = tid >> 5, lane = tid & 31;
  float4* row = (float4*)(out + (size_t)blockIdx.x * Ssz);
  float4 v = row[tid];
  float m = fmaxf(fmaxf(v.x, v.y), fmaxf(v.z, v.w));
#pragma unroll
  for (int o = 16; o; o >>= 1) m = fmaxf(m, __shfl_xor_sync(0xffffffffu, m, o));
  if (lane == 0) rmx[w] = m;
  __syncthreads();
  m = rmx[0];
#pragma unroll
  for (int q = 1; q < 8; q++) m = fmaxf(m, rmx[q]);
  float4 e;
  e.x = expf(v.x - m); e.y = expf(v.y - m);
  e.z = expf(v.z - m); e.w = expf(v.w - m);
  float s = (e.x + e.y) + (e.z + e.w);
#pragma unroll
  for (int o = 16; o; o >>= 1) s += __shfl_xor_sync(0xffffffffu, s, o);
  if (lane == 0) rsm[w] = s;
  __syncthreads();
  s = 0.f;
#pragma unroll
  for (int q = 0; q < 8; q++) s += rsm[q];
  float inv = 1.f / s;
  e.x *= inv; e.y *= inv; e.z *= inv; e.w *= inv;
  row[tid] = e;
}

// ---------------------------------------------------------------------------
extern "C" void kernel_launch(void* const* d_in, const int* in_sizes, int n_in,
                              void* d_out, int out_size)
{
  const float* enc  = (const float*)d_in[0];  // [32,1024,256]
  const float* W_ih = (const float*)d_in[1];  // [1024,256]
  const float* W_hh = (const float*)d_in[2];  // [1024,256]
  const float* b_ih = (const float*)d_in[3];  // [1024]
  const float* b_hh = (const float*)d_in[4];  // [1024]
  float* out = (float*)d_out;                 // [32,1024,1024]

  // Phase 1: WX = enc @ W_ih^T + biases
  dim3 g1(G4 / 64, (Bsz * Ssz) / 64);
  wx_gemm<<<g1, 256>>>(enc, W_ih, b_ih, b_hh);

  // Phase 2: sequential decoder, 32 clusters x 4 CTAs x 512 threads
  const int smem_bytes = (NSM * 256 + 512 + 64 + 256 + 256 + 8 + 8 + 4 + 4) * 4;
  cudaFuncSetAttribute(decoder_main,
                       cudaFuncAttributeMaxDynamicSharedMemorySize, smem_bytes);
  decoder_main<<<Bsz * 4, 512, smem_bytes>>>(enc, W_hh, b_ih, b_hh, out);

  // Phase 3: softmax normalize (off the sequential critical path)
  softmax_finalize<<<Bsz * Ssz, 256>>>(out);
}

// round 9
// speedup vs baseline: 1.3264x; 1.3264x over previous
#include <cuda_runtime.h>
#include <cuda_bf16.h>
#include <cooperative_groups.h>
#include <math.h>

namespace cg = cooperative_groups;

#define Bsz 32
#define Ssz 1024
#define Hsz 256
#define G4  1024
#define KS  216        // W_hh^T k-slices in SMEM
#define KR  40         // W_hh^T k-slices in registers (KS+KR = 256)
#define C0  0.00215f   // > 2^-9 * 1.1 : sound bf16+fp32 error coefficient

// static scratch
__device__ float         g_WX[(size_t)Bsz * Ssz * G4];   // enc@W_ih^T + biases
__device__ float         g_H [(size_t)Bsz * Ssz * Hsz];  // h(t+1) history
__device__ __nv_bfloat16 g_encT[(size_t)Bsz * Hsz * Ssz];// encT[b][k][s]
__device__ float         g_WT[Hsz * G4];                 // W_hh^T [k][j]
__device__ float         g_norm[Bsz * Ssz];              // ||enc_row||

__device__ __forceinline__ float dot8(float4 a0, float4 a1, float4 h0, float4 h1) {
  return a0.x*h0.x + a0.y*h0.y + a0.z*h0.z + a0.w*h0.w
       + a1.x*h1.x + a1.y*h1.y + a1.z*h1.z + a1.w*h1.w;
}
__device__ __forceinline__ float wsum(float acc) {
#pragma unroll
  for (int o = 16; o; o >>= 1) acc += __shfl_down_sync(0xffffffffu, acc, o);
  return acc;
}

// ---------------------------------------------------------------------------
// Kernel 1: WX = enc @ W_ih^T + (b_ih + b_hh)    (proven R5 GEMM)
// ---------------------------------------------------------------------------
__global__ __launch_bounds__(256) void wx_gemm(
    const float* __restrict__ A, const float* __restrict__ Wb,
    const float* __restrict__ b_ih, const float* __restrict__ b_hh)
{
  __shared__ float As[16][64];
  __shared__ float Bs[16][64];
  const int tid = threadIdx.x;
  const int row0 = blockIdx.y * 64, col0 = blockIdx.x * 64;
  const int lr = tid >> 2, lc = (tid & 3) * 4;
  const int ty = tid >> 4, tx = tid & 15;
  float acc[4][4] = {};
  for (int k0 = 0; k0 < 256; k0 += 16) {
    float4 av = *(const float4*)(A  + (size_t)(row0 + lr) * 256 + k0 + lc);
    float4 bv = *(const float4*)(Wb + (size_t)(col0 + lr) * 256 + k0 + lc);
    As[lc+0][lr]=av.x; As[lc+1][lr]=av.y; As[lc+2][lr]=av.z; As[lc+3][lr]=av.w;
    Bs[lc+0][lr]=bv.x; Bs[lc+1][lr]=bv.y; Bs[lc+2][lr]=bv.z; Bs[lc+3][lr]=bv.w;
    __syncthreads();
#pragma unroll
    for (int kk = 0; kk < 16; kk++) {
      float4 a4 = *(const float4*)&As[kk][ty*4];
      float4 b4 = *(const float4*)&Bs[kk][tx*4];
      float a[4]={a4.x,a4.y,a4.z,a4.w}, bb[4]={b4.x,b4.y,b4.z,b4.w};
#pragma unroll
      for (int i = 0; i < 4; i++)
#pragma unroll
        for (int j = 0; j < 4; j++) acc[i][j] += a[i]*bb[j];
    }
    __syncthreads();
  }
#pragma unroll
  for (int i = 0; i < 4; i++) {
    int rr = row0 + ty*4 + i;
#pragma unroll
    for (int j = 0; j < 4; j++) {
      int cc = col0 + tx*4 + j;
      g_WX[(size_t)rr * G4 + cc] = acc[i][j] + b_ih[cc] + b_hh[cc];
    }
  }
}

// ---------------------------------------------------------------------------
// Kernel 1b: post-loop scores GEMM  out[b][t][s] = g_H[b][t]·enc[b][s]
// ---------------------------------------------------------------------------
__global__ __launch_bounds__(256) void score_gemm(
    const float* __restrict__ enc, float* __restrict__ out)
{
  __shared__ float As[16][64];
  __shared__ float Bs[16][64];
  const int bz = blockIdx.z;
  const float* A  = g_H + (size_t)bz * Ssz * Hsz;   // rows = t
  const float* Bm = enc + (size_t)bz * Ssz * Hsz;   // rows = s
  float* C = out + (size_t)bz * Ssz * Ssz;
  const int tid = threadIdx.x;
  const int row0 = blockIdx.y * 64, col0 = blockIdx.x * 64;
  const int lr = tid >> 2, lc = (tid & 3) * 4;
  const int ty = tid >> 4, tx = tid & 15;
  float acc[4][4] = {};
  for (int k0 = 0; k0 < 256; k0 += 16) {
    float4 av = *(const float4*)(A  + (size_t)(row0 + lr) * 256 + k0 + lc);
    float4 bv = *(const float4*)(Bm + (size_t)(col0 + lr) * 256 + k0 + lc);
    As[lc+0][lr]=av.x; As[lc+1][lr]=av.y; As[lc+2][lr]=av.z; As[lc+3][lr]=av.w;
    Bs[lc+0][lr]=bv.x; Bs[lc+1][lr]=bv.y; Bs[lc+2][lr]=bv.z; Bs[lc+3][lr]=bv.w;
    __syncthreads();
#pragma unroll
    for (int kk = 0; kk < 16; kk++) {
      float4 a4 = *(const float4*)&As[kk][ty*4];
      float4 b4 = *(const float4*)&Bs[kk][tx*4];
      float a[4]={a4.x,a4.y,a4.z,a4.w}, bb[4]={b4.x,b4.y,b4.z,b4.w};
#pragma unroll
      for (int i = 0; i < 4; i++)
#pragma unroll
        for (int j = 0; j < 4; j++) acc[i][j] += a[i]*bb[j];
    }
    __syncthreads();
  }
#pragma unroll
  for (int i = 0; i < 4; i++)
#pragma unroll
    for (int j = 0; j < 4; j++)
      C[(size_t)(row0 + ty*4 + i) * Ssz + col0 + tx*4 + j] = acc[i][j];
}

// ---------------------------------------------------------------------------
// Prep kernels
// ---------------------------------------------------------------------------
__global__ void enc_bf_T(const float* __restrict__ enc) {
  __shared__ float tile[32][33];
  const int b = blockIdx.z, s0 = blockIdx.x * 32, k0 = blockIdx.y * 32;
  const int tx = threadIdx.x, ty = threadIdx.y;
  const float* eb = enc + (size_t)b * Ssz * Hsz;
#pragma unroll
  for (int i = 0; i < 32; i += 8)
    tile[ty + i][tx] = eb[(size_t)(s0 + ty + i) * Hsz + k0 + tx];
  __syncthreads();
  __nv_bfloat16* ob = g_encT + (size_t)b * Hsz * Ssz;
#pragma unroll
  for (int i = 0; i < 32; i += 8)
    ob[(size_t)(k0 + ty + i) * Ssz + s0 + tx] = __float2bfloat16_rn(tile[tx][ty + i]);
}

__global__ void whh_T(const float* __restrict__ W_hh) {
  __shared__ float tile[32][33];
  const int j0 = blockIdx.x * 32, k0 = blockIdx.y * 32;
  const int tx = threadIdx.x, ty = threadIdx.y;
#pragma unroll
  for (int i = 0; i < 32; i += 8)
    tile[ty + i][tx] = W_hh[(size_t)(j0 + ty + i) * Hsz + k0 + tx];
  __syncthreads();
#pragma unroll
  for (int i = 0; i < 32; i += 8)
    g_WT[(size_t)(k0 + ty + i) * G4 + j0 + tx] = tile[tx][ty + i];
}

__global__ void row_norms(const float* __restrict__ enc) {
  const int row = blockIdx.x * 8 + (threadIdx.x >> 5);
  const int lane = threadIdx.x & 31;
  const float4* er = (const float4*)(enc + (size_t)row * Hsz);
  float4 a = er[lane], b = er[32 + lane];
  float ss = wsum(dot8(a, b, a, b));
  if (lane == 0) g_norm[row] = sqrtf(ss);
}

// ---------------------------------------------------------------------------
// Kernel 2: sequential decoder. One 4-CTA cluster per batch.
// warps 0-7: bf16 scores (thread = 4 s-cols)  ∥  warps 8-15: fp32 gates
// ---------------------------------------------------------------------------
#define CL_ARRIVE() asm volatile("barrier.cluster.arrive.aligned;" ::: "memory")
#define CL_WAIT()   asm volatile("barrier.cluster.wait.aligned;"   ::: "memory")

__global__ void __cluster_dims__(4, 1, 1) __launch_bounds__(512, 1)
decoder_main(const float* __restrict__ enc,
             const float* __restrict__ b_ih,
             const float* __restrict__ b_hh)
{
  extern __shared__ float sm[];
  float*  Wt       = sm;                    // KS*256  [k][j]
  float*  h_buf    = Wt + KS * 256;         // 2*256
  float*  c_s      = h_buf + 512;           // 64
  float*  gates_s  = c_s + 64;              // 256
  float*  scores_s = gates_s + 256;         // 256
  float*  sp       = scores_s + 256;        // 4*256 partials [kc][s]
  float*  n_sm     = sp + 1024;             // 256
  float*  normh_s  = n_sm + 256;            // 4
  float4* redA     = (float4*)(normh_s + 4);        // 8 (u1,u2,lb,i1)
  float*  red_m    = (float*)(redA + 8);            // 8
  int*    red_i    = (int*)(red_m + 8);             // 8
  float4* tup1     = (float4*)(red_i + 8);          // 4
  float*  tup2m    = (float*)(tup1 + 4);            // 4
  int*    tup2i    = (int*)(tup2m + 4);             // 4

  cg::cluster_group cluster = cg::this_cluster();
  const int tid  = threadIdx.x;
  const int w    = tid >> 5, lane = tid & 31;
  const int r    = blockIdx.x & 3;
  const int b    = blockIdx.x >> 2;

  // ---- init: W^T SMEM slices (k<KS), local gate cols j=0..255 ----
  for (int i = tid; i < KS * 64; i += 512) {
    int k = i >> 6, jq = i & 63;
    int G = (jq >> 4) * 256 + r * 64 + ((jq & 15) << 2);
    ((float4*)Wt)[i] = *(const float4*)(g_WT + (size_t)k * G4 + G);
  }
  // register-resident k-slices (gates threads)
  float wreg[KR];
  int jloc = (w - 8) * 32 + lane;
  if (w >= 8) {
    int G = (jloc >> 6) * 256 + r * 64 + (jloc & 63);
#pragma unroll
    for (int kk = 0; kk < KR; kk++)
      wreg[kk] = g_WT[(size_t)(KS + kk) * G4 + G];
  }
  // row norms for owned s range
  if (tid < 256) n_sm[tid] = g_norm[b * Ssz + r * 256 + tid];

  // ---- prologue: h(1), c(1) from bias-only gates ----
  if (tid < 256) {
    float gi = b_ih[tid]       + b_hh[tid];
    float gg = b_ih[512 + tid] + b_hh[512 + tid];
    float go = b_ih[768 + tid] + b_hh[768 + tid];
    float iv = 1.f / (1.f + expf(-gi));
    float gv = tanhf(gg);
    float ov = 1.f / (1.f + expf(-go));
    h_buf[tid] = ov * tanhf(iv * gv);
  }
  if (tid >= 256 && tid < 320) {
    int j = tid - 256, k = r * 64 + j;
    float gi = b_ih[k] + b_hh[k];
    float gg = b_ih[512 + k] + b_hh[512 + k];
    c_s[j] = (1.f / (1.f + expf(-gi))) * tanhf(gg);
  }
  __syncthreads();
  if (tid < 64) g_H[((size_t)b * Ssz) * Hsz + r * 64 + tid] = h_buf[r * 64 + tid];
  CL_ARRIVE(); CL_WAIT();

  const float* WXb = g_WX + (size_t)b * Ssz * G4;
  const float* encb = enc + (size_t)b * Ssz * Hsz;
  int idx = 0;

#pragma unroll 1
  for (int t = 0; t < Ssz; t++) {
    const int p = t & 1;
    const float* hptr = h_buf + p * 256;
    if (t > 0) CL_WAIT();

    if (w < 8) {
      // ---- bf16 scores: thread owns s = 4*sc .. 4*sc+3, k-range kc*64.. ----
      const int kc = tid >> 6, sc = tid & 63;
      const uint2* pbase = (const uint2*)(g_encT
          + ((size_t)(b * Hsz + kc * 64)) * Ssz + r * 256) + sc;
      const float* hk = hptr + kc * 64;
      float a0 = 0.f, a1 = 0.f, a2 = 0.f, a3 = 0.f;
#pragma unroll 4
      for (int i0 = 0; i0 < 64; i0 += 4) {
        float4 hq = *(const float4*)(hk + i0);
        float hv[4] = {hq.x, hq.y, hq.z, hq.w};
#pragma unroll
        for (int q = 0; q < 4; q++) {
          uint2 u = pbase[(size_t)(i0 + q) * 256];
          float e0 = __uint_as_float(u.x << 16);
          float e1 = __uint_as_float(u.x & 0xFFFF0000u);
          float e2 = __uint_as_float(u.y << 16);
          float e3 = __uint_as_float(u.y & 0xFFFF0000u);
          a0 += e0 * hv[q]; a1 += e1 * hv[q];
          a2 += e2 * hv[q]; a3 += e3 * hv[q];
        }
      }
      ((float4*)sp)[kc * 64 + sc] = make_float4(a0, a1, a2, a3);
    } else {
      if (w == 15) {             // ||h|| for the error bound
        float s2 = 0.f;
#pragma unroll
        for (int q = 0; q < 8; q++) { float hv = hptr[lane + 32*q]; s2 += hv*hv; }
        s2 = wsum(s2);
        if (lane == 0) normh_s[0] = sqrtf(s2);
      }
      // ---- fp32 gates: thread owns gate row jloc ----
      const float* wj = Wt + jloc;
      float acc0 = 0.f, acc1 = 0.f;
#pragma unroll 4
      for (int k0 = 0; k0 < KS; k0 += 4) {
        float4 hq = *(const float4*)(hptr + k0);
        acc0 += wj[(k0+0)*256] * hq.x;  acc1 += wj[(k0+1)*256] * hq.y;
        acc0 += wj[(k0+2)*256] * hq.z;  acc1 += wj[(k0+3)*256] * hq.w;
      }
#pragma unroll
      for (int q = 0; q < KR/4; q++) {
        float4 hq = *(const float4*)(hptr + KS + q*4);
        acc0 += wreg[q*4+0] * hq.x;  acc1 += wreg[q*4+1] * hq.y;
        acc0 += wreg[q*4+2] * hq.z;  acc1 += wreg[q*4+3] * hq.w;
      }
      gates_s[jloc] = acc0 + acc1;
    }
    __syncthreads();

    // ---- per-CTA top-2(ub) + max(lb), butterfly, no self-merge ----
    if (tid < 256) {
      const int s = tid;
      float scv = sp[s] + sp[256 + s] + sp[512 + s] + sp[768 + s];
      scores_s[s] = scv;
      float E  = C0 * n_sm[s] * normh_s[0];
      float lb = scv - E;
      float u1 = scv + E, u2 = -INFINITY; int i1 = s;
#pragma unroll
      for (int o = 16; o; o >>= 1) {
        float ou1 = __shfl_xor_sync(0xffffffffu, u1, o);
        float ou2 = __shfl_xor_sync(0xffffffffu, u2, o);
        int   oi1 = __shfl_xor_sync(0xffffffffu, i1, o);
        float olb = __shfl_xor_sync(0xffffffffu, lb, o);
        lb = fmaxf(lb, olb);
        if (ou1 > u1) { u2 = fmaxf(u1, ou2); u1 = ou1; i1 = oi1; }
        else { u2 = fmaxf(u2, ou1); if (ou1 == u1) i1 = min(i1, oi1); }
      }
      if (lane == 0) redA[w] = make_float4(u1, u2, lb, __int_as_float(i1));
    }
    __syncthreads();
    if (tid == 0) {
      float4 t0 = redA[0];
      float u1 = t0.x, u2 = t0.y, lbm = t0.z; int i1 = __float_as_int(t0.w);
#pragma unroll
      for (int q = 1; q < 8; q++) {
        float4 tq = redA[q];
        lbm = fmaxf(lbm, tq.z);
        float ou1 = tq.x, ou2 = tq.y; int oi1 = __float_as_int(tq.w);
        if (ou1 > u1) { u2 = fmaxf(u1, ou2); u1 = ou1; i1 = oi1; }
        else { u2 = fmaxf(u2, ou1); if (ou1 == u1) i1 = min(i1, oi1); }
      }
      float4 pub = make_float4(u1, u2, lbm, __int_as_float(r * 256 + i1));
#pragma unroll
      for (int dst = 0; dst < 4; dst++)
        *cluster.map_shared_rank(&tup1[r], dst) = pub;
    }
    CL_ARRIVE(); CL_WAIT();   // tuples visible cluster-wide

    // ---- decide argmax (fast: unique candidate; slow: fp32 rescore) ----
    float4 q0 = tup1[0], q1 = tup1[1], q2 = tup1[2], q3 = tup1[3];
    float L = fmaxf(fmaxf(q0.z, q1.z), fmaxf(q2.z, q3.z));
    float u1a[4] = {q0.x, q1.x, q2.x, q3.x};
    float u2a[4] = {q0.y, q1.y, q2.y, q3.y};
    float i1a[4] = {q0.w, q1.w, q2.w, q3.w};
    int cnt = 0, rstar = 0;
#pragma unroll
    for (int q = 3; q >= 0; q--)
      if (u1a[q] >= L) { cnt++; rstar = q; }
    bool fast = (cnt == 1) && (u2a[rstar] < L);

    if (fast) {
      idx = __float_as_int(i1a[rstar]);
    } else {
      // slow path (uniform across cluster): rescore all candidates in fp32
      if (w < 8) {
        const int s = tid;
        float E  = C0 * n_sm[s] * normh_s[0];
        float ub = scores_s[s] + E;
        unsigned mask = __ballot_sync(0xffffffffu, ub >= L);
        float best = -INFINITY; int bidx = 0x7fffffff;
        const float4* h4p = (const float4*)hptr;
        float4 h0w = h4p[lane], h1w = h4p[32 + lane];
        while (mask) {
          int bit = __ffs(mask) - 1; mask &= mask - 1;
          int s0 = w * 32 + bit;
          const float4* er = (const float4*)(encb + (size_t)(r * 256 + s0) * Hsz);
          float val = wsum(dot8(er[lane], er[32 + lane], h0w, h1w));
          if (lane == 0 && val > best) { best = val; bidx = s0; }
        }
        if (lane == 0) {
          red_m[w] = best;
          red_i[w] = (bidx == 0x7fffffff) ? 0x7fffffff : r * 256 + bidx;
        }
      }
      __syncthreads();
      if (tid == 0) {
        float gv = red_m[0]; int gi = red_i[0];
#pragma unroll
        for (int q = 1; q < 8; q++) {
          float v = red_m[q]; int ii = red_i[q];
          if (v > gv || (v == gv && ii < gi)) { gv = v; gi = ii; }
        }
#pragma unroll
        for (int dst = 0; dst < 4; dst++) {
          *cluster.map_shared_rank(&tup2m[r], dst) = gv;
          *cluster.map_shared_rank(&tup2i[r], dst) = gi;
        }
      }
      CL_ARRIVE(); CL_WAIT();
      float gm = tup2m[0]; idx = tup2i[0];
#pragma unroll
      for (int q = 1; q < 4; q++) {
        float mq = tup2m[q]; int iq = tup2i[q];
        if (mq > gm || (mq == gm && iq < idx)) { gm = mq; idx = iq; }
      }
    }

    // ---- cell: h(t+2), record to g_H, DSMEM-broadcast ----
    if (t < Ssz - 1) {
      if (tid >= 256 && tid < 320) {
        int j = tid - 256;
        const float* wxr = WXb + (size_t)idx * G4 + r * 64 + j;
        float gi = gates_s[j]        + wxr[0];
        float gf = gates_s[64  + j]  + wxr[256];
        float gg = gates_s[128 + j]  + wxr[512];
        float go = gates_s[192 + j]  + wxr[768];
        float iv = 1.f / (1.f + expf(-gi));
        float fv = 1.f / (1.f + expf(-gf));
        float gv = tanhf(gg);
        float ov = 1.f / (1.f + expf(-go));
        float c  = fv * c_s[j] + iv * gv;
        c_s[j] = c;
        float hk = ov * tanhf(c);
        g_H[((size_t)b * Ssz + t + 1) * Hsz + r * 64 + j] = hk;
        float* hl = &h_buf[(p ^ 1) * 256 + r * 64 + j];
#pragma unroll
        for (int dst = 0; dst < 4; dst++)
          *cluster.map_shared_rank(hl, dst) = hk;
      }
      CL_ARRIVE();
    }
  }
}

// ---------------------------------------------------------------------------
// Kernel 4: softmax over out rows (proven R7)
// ---------------------------------------------------------------------------
__global__ __launch_bounds__(256) void softmax_finalize(float* __restrict__ out)
{
  __shared__ float rmx[8];
  __shared__ float rsm[8];
  const int tid = threadIdx.x, w = tid >> 5, lane = tid & 31;
  float4* row = (float4*)(out + (size_t)blockIdx.x * Ssz);
  float4 v = row[tid];
  float m = fmaxf(fmaxf(v.x, v.y), fmaxf(v.z, v.w));
#pragma unroll
  for (int o = 16; o; o >>= 1) m = fmaxf(m, __shfl_xor_sync(0xffffffffu, m, o));
  if (lane == 0) rmx[w] = m;
  __syncthreads();
  m = rmx[0];
#pragma unroll
  for (int q = 1; q < 8; q++) m = fmaxf(m, rmx[q]);
  float4 e;
  e.x = expf(v.x - m); e.y = expf(v.y - m);
  e.z = expf(v.z - m); e.w = expf(v.w - m);
  float s = (e.x + e.y) + (e.z + e.w);
#pragma unroll
  for (int o = 16; o; o >>= 1) s += __shfl_xor_sync(0xffffffffu, s, o);
  if (lane == 0) rsm[w] = s;
  __syncthreads();
  s = 0.f;
#pragma unroll
  for (int q = 0; q < 8; q++) s += rsm[q];
  float inv = 1.f / s;
  e.x *= inv; e.y *= inv; e.z *= inv; e.w *= inv;
  row[tid] = e;
}

// ---------------------------------------------------------------------------
extern "C" void kernel_launch(void* const* d_in, const int* in_sizes, int n_in,
                              void* d_out, int out_size)
{
  const float* enc  = (const float*)d_in[0];
  const float* W_ih = (const float*)d_in[1];
  const float* W_hh = (const float*)d_in[2];
  const float* b_ih = (const float*)d_in[3];
  const float* b_hh = (const float*)d_in[4];
  float* out = (float*)d_out;

  // preps
  dim3 g1(G4 / 64, (Bsz * Ssz) / 64);
  wx_gemm<<<g1, 256>>>(enc, W_ih, b_ih, b_hh);
  row_norms<<<(Bsz * Ssz) / 8, 256>>>(enc);
  enc_bf_T<<<dim3(Ssz / 32, Hsz / 32, Bsz), dim3(32, 8)>>>(enc);
  whh_T<<<dim3(G4 / 32, Hsz / 32), dim3(32, 8)>>>(W_hh);

  // sequential decoder
  const int smem_bytes = (KS * 256 + 512 + 64 + 256 + 256 + 1024 + 256 + 4
                          + 8 * 4 + 8 + 8 + 4 * 4 + 4 + 4) * 4;
  cudaFuncSetAttribute(decoder_main,
                       cudaFuncAttributeMaxDynamicSharedMemorySize, smem_bytes);
  decoder_main<<<Bsz * 4, 512, smem_bytes>>>(enc, b_ih, b_hh);

  // probs off the critical path
  score_gemm<<<dim3(Ssz / 64, Ssz / 64, Bsz), 256>>>(enc, out);
  softmax_finalize<<<Bsz * Ssz, 256>>>(out);
}